// round 11
// baseline (speedup 1.0000x reference)
#include <cuda_runtime.h>
#include <cuda_fp16.h>
#include <cstdint>

#define NN 50000
#define NE 640000
#define DIM 128

// ---------------- scratch (device globals: allocation-free rule) ----------------
__device__ float   g_Ax[NN * DIM];           // A output, fp32
__device__ __half  g_Bh[NN * DIM];           // B output, fp16
__device__ __half  g_Dh[NN * DIM];           // D output, fp16
__device__ __half  g_Eh[NN * DIM];           // E output, fp16
__device__ __half2 g_EB2[NN * DIM];          // interleaved {E_c, B_c} per column
__device__ __half2 g_ND[NN * DIM];           // interleaved {num_c, den_c} accumulators
__device__ uint2   g_Wf[5][16 * 16 * 32];    // fragment-packed tf32 weights: A,B,D,E,C
__device__ int     g_i64;

// ---------------- helpers ----------------
__device__ __forceinline__ unsigned f2tf32(float f) {
    unsigned u;
    asm("cvt.rna.tf32.f32 %0, %1;" : "=r"(u) : "f"(f));
    return u;
}

__device__ __forceinline__ void mma_tf32(float c[4], const unsigned a[4],
                                         unsigned b0, unsigned b1) {
    asm volatile(
        "mma.sync.aligned.m16n8k8.row.col.f32.tf32.tf32.f32 "
        "{%0,%1,%2,%3}, {%4,%5,%6,%7}, {%8,%9}, {%0,%1,%2,%3};"
        : "+f"(c[0]), "+f"(c[1]), "+f"(c[2]), "+f"(c[3])
        : "r"(a[0]), "r"(a[1]), "r"(a[2]), "r"(a[3]), "r"(b0), "r"(b1));
}

__device__ __forceinline__ float sigmoidf_(float v) {
    return 1.0f / (1.0f + __expf(-v));
}

__device__ __forceinline__ unsigned pack_h2(float a, float b) {
    __half2 h = __floats2half2_rn(a, b);
    return *reinterpret_cast<unsigned*>(&h);
}

__device__ __forceinline__ unsigned h2u(__half2 h) {
    return *reinterpret_cast<unsigned*>(&h);
}

// 64x128x128 GEMM core. sA: [64][132] 32-bit operands in smem (tf32 or raw fp32 bits).
__device__ __forceinline__ void gemm_tile(const unsigned* sA, const uint2* __restrict__ Wf,
                                          float acc[2][4][4], int mBase, int nb,
                                          int r, int c, int lane) {
#pragma unroll 4
    for (int ks = 0; ks < 16; ks++) {
        uint2 b[4];
#pragma unroll
        for (int tj = 0; tj < 4; tj++)
            b[tj] = __ldg(&Wf[(ks * 16 + nb + tj) * 32 + lane]);
        unsigned a[2][4];
#pragma unroll
        for (int ti = 0; ti < 2; ti++) {
            const unsigned* ap = &sA[(mBase + ti * 16 + r) * 132 + ks * 8 + c];
            a[ti][0] = ap[0];
            a[ti][1] = ap[8 * 132];
            a[ti][2] = ap[4];
            a[ti][3] = ap[8 * 132 + 4];
        }
#pragma unroll
        for (int ti = 0; ti < 2; ti++)
#pragma unroll
            for (int tj = 0; tj < 4; tj++)
                mma_tf32(acc[ti][tj], a[ti], b[tj].x, b[tj].y);
    }
}

static const int SMEM_TILE = 64 * 132 * 4;  // 33792 B (node + edge kernels)

// ---------------- kernel 0: zero g_ND + detect edge_index dtype ----------------
__global__ void zero_detect_kernel(const unsigned* __restrict__ w) {
    const size_t i = (size_t)blockIdx.x * 256 + threadIdx.x;  // uint4 index over g_ND
    uint4 z = make_uint4(0u, 0u, 0u, 0u);
    ((uint4*)g_ND)[i] = z;
    if (blockIdx.x == 0 && threadIdx.x < 32) {
        unsigned acc = 0;
        for (int k = threadIdx.x; k < 1024; k += 32) acc |= w[2 * k + 1];
#pragma unroll
        for (int o = 16; o; o >>= 1) acc |= __shfl_xor_sync(0xffffffffu, acc, o);
        if (threadIdx.x == 0) g_i64 = (acc == 0) ? 1 : 0;
    }
}

// ---------------- kernel 1: pack weights into fragment layout (tf32) ----------------
__global__ void prep_kernel(const float* __restrict__ W0, const float* __restrict__ W1,
                            const float* __restrict__ W2, const float* __restrict__ W3,
                            const float* __restrict__ W4) {
    const float* Ws[5] = {W0, W1, W2, W3, W4};
    const int lane = threadIdx.x;
    const int g = blockIdx.x;      // ks*16+ng
    const int mat = blockIdx.y;
    const int ks = g >> 4, ng = g & 15;
    const int r = lane >> 2, c = lane & 3;
    const float* W = Ws[mat];
    const int n = ng * 8 + r;
    const int k = ks * 8 + c;
    uint2 v;
    v.x = f2tf32(W[n * DIM + k]);
    v.y = f2tf32(W[n * DIM + k + 4]);
    g_Wf[mat][g * 32 + lane] = v;
}

// ---------------- kernel 2: node GEMMs, one j per block ----------------
// j = blockIdx.y: 0->g_Ax fp32, 1->g_Bh half2, 2->g_Dh half2, 3->g_Eh half2
__global__ void __launch_bounds__(256, 4) node_gemm_kernel(
    const float* __restrict__ x,
    const float* __restrict__ b0, const float* __restrict__ b1,
    const float* __restrict__ b2, const float* __restrict__ b3) {
    extern __shared__ unsigned smem[];
    unsigned* sX = smem;  // 64*132 words (tf32 x tile)

    const int tid = threadIdx.x;
    const int m0 = blockIdx.x * 64;
    const int j = blockIdx.y;

    const float* bias = (j == 0) ? b0 : (j == 1) ? b1 : (j == 2) ? b2 : b3;
    const uint2* Wf = g_Wf[j];

    for (int i = tid; i < 64 * 32; i += 256) {
        int row = i >> 5, c4 = (i & 31) << 2;
        float4 v = make_float4(0.f, 0.f, 0.f, 0.f);
        if (m0 + row < NN) v = *(const float4*)&x[(size_t)(m0 + row) * DIM + c4];
        unsigned* p = &sX[row * 132 + c4];
        p[0] = f2tf32(v.x); p[1] = f2tf32(v.y); p[2] = f2tf32(v.z); p[3] = f2tf32(v.w);
    }
    __syncthreads();

    const int lane = tid & 31, wid = tid >> 5;
    const int r = lane >> 2, c = lane & 3;
    const int mBase = (wid & 1) * 32;
    const int nBase = (wid >> 1) * 32;
    const int nb = (wid >> 1) * 4;

    float acc[2][4][4];
#pragma unroll
    for (int tj = 0; tj < 4; tj++) {
        int n0 = nBase + tj * 8 + c * 2;
        float bv0 = __ldg(&bias[n0]), bv1 = __ldg(&bias[n0 + 1]);
#pragma unroll
        for (int ti = 0; ti < 2; ti++) {
            acc[ti][tj][0] = bv0; acc[ti][tj][1] = bv1;
            acc[ti][tj][2] = bv0; acc[ti][tj][3] = bv1;
        }
    }

    gemm_tile(sX, Wf, acc, mBase, nb, r, c, lane);

    __half* outH = (j == 1) ? g_Bh : (j == 2) ? g_Dh : g_Eh;
#pragma unroll
    for (int ti = 0; ti < 2; ti++) {
#pragma unroll
        for (int half_i = 0; half_i < 2; half_i++) {
            const int m = m0 + mBase + ti * 16 + r + half_i * 8;
            if (m >= NN) continue;
#pragma unroll
            for (int tj = 0; tj < 4; tj++) {
                const int n0 = nBase + tj * 8 + c * 2;
                const float v0 = acc[ti][tj][half_i * 2];
                const float v1 = acc[ti][tj][half_i * 2 + 1];
                if (j == 0) {
                    *(float2*)&g_Ax[(size_t)m * DIM + n0] = make_float2(v0, v1);
                } else {
                    *(__half2*)&outH[(size_t)m * DIM + n0] = __floats2half2_rn(v0, v1);
                }
            }
        }
    }
}

// ---------------- kernel 2b: interleave E/B -> g_EB2 (coalesced stream, ~8us) ----------------
__global__ void interleave_kernel() {
    const size_t i = (size_t)blockIdx.x * 256 + threadIdx.x;  // 4-column index
    const uint2 e2 = ((const uint2*)g_Eh)[i];
    const uint2 b2 = ((const uint2*)g_Bh)[i];
    const __half2 eh01 = *(const __half2*)&e2.x;
    const __half2 eh23 = *(const __half2*)&e2.y;
    const __half2 bh01 = *(const __half2*)&b2.x;
    const __half2 bh23 = *(const __half2*)&b2.y;
    uint4 o;
    o.x = h2u(__lows2half2(eh01, bh01));   // {e0, b0}
    o.y = h2u(__highs2half2(eh01, bh01));  // {e1, b1}
    o.z = h2u(__lows2half2(eh23, bh23));   // {e2, b2}
    o.w = h2u(__highs2half2(eh23, bh23));  // {e3, b3}
    ((uint4*)g_EB2)[i] = o;
}

// ---------------- kernel 3: fused edge kernel ----------------
// e staged RAW fp32 in sE (mma truncates); one 16B EB gather + one 8B D gather +
// one v4.f16x2 red into interleaved {num,den} per iteration.
__global__ void __launch_bounds__(256, 4) edge_kernel(
    const float* __restrict__ e,
    const float* __restrict__ Cb,
    const void* __restrict__ eidx,
    const float* __restrict__ beg, const float* __restrict__ beb,
    const float* __restrict__ bem, const float* __restrict__ bev,
    float* __restrict__ e_out) {
    extern __shared__ unsigned smem[];
    unsigned* sE = smem;       // raw fp32 e tile; aliased by sO after GEMM
    float* sO = (float*)smem;  // fp32 Ce tile (overwrites sE)

    const int tid = threadIdx.x;
    const size_t eBase = (size_t)blockIdx.x * 64;
    const uint2* Wf = g_Wf[4];

    for (int i = tid; i < 64 * 32; i += 256) {
        int row = i >> 5, c4 = (i & 31) << 2;
        float4 v = *(const float4*)&e[(eBase + row) * DIM + c4];
        float* p = (float*)&sE[row * 132 + c4];
        p[0] = v.x; p[1] = v.y; p[2] = v.z; p[3] = v.w;
    }
    __syncthreads();

    const int lane = tid & 31, wid = tid >> 5;
    const int r = lane >> 2, c = lane & 3;
    const int mBase = (wid & 1) * 32;
    const int nBase = (wid >> 1) * 32;
    const int nb = (wid >> 1) * 4;

    float acc[2][4][4];
#pragma unroll
    for (int tj = 0; tj < 4; tj++) {
        int n0 = nBase + tj * 8 + c * 2;
        float bv0 = __ldg(&Cb[n0]), bv1 = __ldg(&Cb[n0 + 1]);
#pragma unroll
        for (int ti = 0; ti < 2; ti++) {
            acc[ti][tj][0] = bv0; acc[ti][tj][1] = bv1;
            acc[ti][tj][2] = bv0; acc[ti][tj][3] = bv1;
        }
    }

    gemm_tile(sE, Wf, acc, mBase, nb, r, c, lane);

    __syncthreads();  // all sE reads done -> safe to overwrite with sO
#pragma unroll
    for (int ti = 0; ti < 2; ti++) {
        int m = mBase + ti * 16 + r;
#pragma unroll
        for (int tj = 0; tj < 4; tj++) {
            int n0 = nBase + tj * 8 + c * 2;
            sO[m * 132 + n0]           = acc[ti][tj][0];
            sO[m * 132 + n0 + 1]       = acc[ti][tj][1];
            sO[(m + 8) * 132 + n0]     = acc[ti][tj][2];
            sO[(m + 8) * 132 + n0 + 1] = acc[ti][tj][3];
        }
    }
    __syncthreads();

    // ---- epilogue: warp w handles edges w*8..w*8+7, lane owns cols 4*lane..+3
    const int n = lane * 4;
    const float4 gm = *(const float4*)&beg[n];
    const float4 bt = *(const float4*)&beb[n];
    const float4 mn = *(const float4*)&bem[n];
    const float4 vr = *(const float4*)&bev[n];
    const float s0c = gm.x * rsqrtf(vr.x + 1e-5f);
    const float s1c = gm.y * rsqrtf(vr.y + 1e-5f);
    const float s2c = gm.z * rsqrtf(vr.z + 1e-5f);
    const float s3c = gm.w * rsqrtf(vr.w + 1e-5f);
    const float h0c = bt.x - mn.x * s0c;
    const float h1c = bt.y - mn.y * s1c;
    const float h2c = bt.z - mn.z * s2c;
    const float h3c = bt.w - mn.w * s3c;

    const int flag = g_i64;
    const long long* i64p = (const long long*)eidx;
    const int* i32p = (const int*)eidx;

    int srcs[8], dsts[8];
    if (flag) {
#pragma unroll
        for (int mi = 0; mi < 8; mi++) {
            const size_t ge = eBase + wid * 8 + mi;
            srcs[mi] = (int)__ldg(&i64p[ge]);
            dsts[mi] = (int)__ldg(&i64p[NE + ge]);
        }
    } else {
#pragma unroll
        for (int mi = 0; mi < 8; mi++) {
            const size_t ge = eBase + wid * 8 + mi;
            srcs[mi] = __ldg(&i32p[ge]);
            dsts[mi] = __ldg(&i32p[NE + ge]);
        }
    }

#pragma unroll
    for (int mi = 0; mi < 8; mi++) {
        const int m = wid * 8 + mi;
        const size_t ge = eBase + m;
        const int srcI = srcs[mi], dstI = dsts[mi];

        // one 16B gather: {E,B} x 4 cols; one 8B gather: D x 4 cols
        const uint4 ebu = __ldg((const uint4*)&g_EB2[(size_t)srcI * DIM + n]);
        const uint2 dhu = __ldg((const uint2*)&g_Dh[(size_t)dstI * DIM + n]);

        const float2 eb0 = __half22float2(*(const __half2*)&ebu.x);  // {ex0, bx0}
        const float2 eb1 = __half22float2(*(const __half2*)&ebu.y);
        const float2 eb2 = __half22float2(*(const __half2*)&ebu.z);
        const float2 eb3 = __half22float2(*(const __half2*)&ebu.w);
        const float2 d01 = __half22float2(*(const __half2*)&dhu.x);
        const float2 d23 = __half22float2(*(const __half2*)&dhu.y);

        const float4 ce = *(const float4*)&sO[m * 132 + n];

        const float e0 = ce.x + d01.x + eb0.x;
        const float e1 = ce.y + d01.y + eb1.x;
        const float e2 = ce.z + d23.x + eb2.x;
        const float e3 = ce.w + d23.y + eb3.x;

        const float sg0 = sigmoidf_(e0);
        const float sg1 = sigmoidf_(e1);
        const float sg2 = sigmoidf_(e2);
        const float sg3 = sigmoidf_(e3);

        // single 16B red into interleaved {num, den} accumulators
        const unsigned nd0 = pack_h2(sg0 * eb0.y, sg0);
        const unsigned nd1 = pack_h2(sg1 * eb1.y, sg1);
        const unsigned nd2 = pack_h2(sg2 * eb2.y, sg2);
        const unsigned nd3 = pack_h2(sg3 * eb3.y, sg3);
        __half2* ndp = &g_ND[(size_t)dstI * DIM + n];
        asm volatile("red.global.add.noftz.v4.f16x2 [%0], {%1,%2,%3,%4};"
                     :: "l"(ndp), "r"(nd0), "r"(nd1), "r"(nd2), "r"(nd3)
                     : "memory");

        // residual re-read: mostly L2-hit (staged moments ago); .cs = evict-first
        float4 ev;
        asm volatile("ld.global.cs.v4.f32 {%0,%1,%2,%3}, [%4];"
                     : "=f"(ev.x), "=f"(ev.y), "=f"(ev.z), "=f"(ev.w)
                     : "l"(&e[ge * DIM + n]));
        float4 o;
        o.x = ev.x + fmaxf(0.f, e0 * s0c + h0c);
        o.y = ev.y + fmaxf(0.f, e1 * s1c + h1c);
        o.z = ev.z + fmaxf(0.f, e2 * s2c + h2c);
        o.w = ev.w + fmaxf(0.f, e3 * s3c + h3c);
        asm volatile("st.global.cs.v4.f32 [%0], {%1,%2,%3,%4};"
                     :: "l"(&e_out[ge * DIM + n]),
                        "f"(o.x), "f"(o.y), "f"(o.z), "f"(o.w)
                     : "memory");
    }
}

// ---------------- kernel 4: node update ----------------
__global__ void update_kernel(const float* __restrict__ x,
                              const float* __restrict__ bxg, const float* __restrict__ bxb,
                              const float* __restrict__ bxm, const float* __restrict__ bxv,
                              float* __restrict__ x_out) {
    const size_t i = (size_t)blockIdx.x * 256 + threadIdx.x;  // 4-column index
    const int c4 = ((int)i & 31) << 2;

    const uint4 ndu = ((const uint4*)g_ND)[i];
    const float2 nd0 = __half22float2(*(const __half2*)&ndu.x);  // {num0, den0}
    const float2 nd1 = __half22float2(*(const __half2*)&ndu.y);
    const float2 nd2 = __half22float2(*(const __half2*)&ndu.z);
    const float2 nd3 = __half22float2(*(const __half2*)&ndu.w);

    const float4 ax = ((const float4*)g_Ax)[i];
    const float4 xv = ((const float4*)x)[i];

    const float4 gm = *(const float4*)&bxg[c4];
    const float4 bt = *(const float4*)&bxb[c4];
    const float4 mn = *(const float4*)&bxm[c4];
    const float4 vr = *(const float4*)&bxv[c4];

    const float s0 = gm.x * rsqrtf(vr.x + 1e-5f);
    const float s1 = gm.y * rsqrtf(vr.y + 1e-5f);
    const float s2 = gm.z * rsqrtf(vr.z + 1e-5f);
    const float s3 = gm.w * rsqrtf(vr.w + 1e-5f);
    const float h0 = bt.x - mn.x * s0;
    const float h1 = bt.y - mn.y * s1;
    const float h2 = bt.z - mn.z * s2;
    const float h3 = bt.w - mn.w * s3;

    const float v0 = ax.x + nd0.x / (nd0.y + 1e-6f);
    const float v1 = ax.y + nd1.x / (nd1.y + 1e-6f);
    const float v2 = ax.z + nd2.x / (nd2.y + 1e-6f);
    const float v3 = ax.w + nd3.x / (nd3.y + 1e-6f);

    float4 o;
    o.x = xv.x + fmaxf(0.f, v0 * s0 + h0);
    o.y = xv.y + fmaxf(0.f, v1 * s1 + h1);
    o.z = xv.z + fmaxf(0.f, v2 * s2 + h2);
    o.w = xv.w + fmaxf(0.f, v3 * s3 + h3);
    asm volatile("st.global.cs.v4.f32 [%0], {%1,%2,%3,%4};"
                 :: "l"(&((float4*)x_out)[i]),
                    "f"(o.x), "f"(o.y), "f"(o.z), "f"(o.w)
                 : "memory");
}

// ---------------- launch ----------------
extern "C" void kernel_launch(void* const* d_in, const int* in_sizes, int n_in,
                              void* d_out, int out_size) {
    const float* x  = (const float*)d_in[0];
    const float* e  = (const float*)d_in[1];
    const float* Aw = (const float*)d_in[2];
    const float* Ab = (const float*)d_in[3];
    const float* Bw = (const float*)d_in[4];
    const float* Bb = (const float*)d_in[5];
    const float* Cw = (const float*)d_in[6];
    const float* Cb = (const float*)d_in[7];
    const float* Dw = (const float*)d_in[8];
    const float* Db = (const float*)d_in[9];
    const float* Ew = (const float*)d_in[10];
    const float* Eb = (const float*)d_in[11];
    const float* bxg = (const float*)d_in[12];
    const float* bxb = (const float*)d_in[13];
    const float* bxm = (const float*)d_in[14];
    const float* bxv = (const float*)d_in[15];
    const float* beg = (const float*)d_in[16];
    const float* beb = (const float*)d_in[17];
    const float* bem = (const float*)d_in[18];
    const float* bev = (const float*)d_in[19];
    const void*  eidx = d_in[20];

    float* x_out = (float*)d_out;
    float* e_out = x_out + (size_t)NN * DIM;

    zero_detect_kernel<<<6250, 256>>>((const unsigned*)eidx);
    // weight order: 0:A 1:B 2:D 3:E 4:C
    prep_kernel<<<dim3(256, 5), 32>>>(Aw, Bw, Dw, Ew, Cw);
    node_gemm_kernel<<<dim3(782, 4), 256, SMEM_TILE>>>(x, Ab, Bb, Db, Eb);
    interleave_kernel<<<6250, 256>>>();
    edge_kernel<<<10000, 256, SMEM_TILE>>>(e, Cb, eidx, beg, beb, bem, bev, e_out);
    update_kernel<<<6250, 256>>>(x, bxg, bxb, bxm, bxv, x_out);
}